// round 5
// baseline (speedup 1.0000x reference)
#include <cuda_runtime.h>
#include <cstdint>

// ---------------- scratch (device globals; no allocations) ----------------
__device__ float g_c1[32u * 128u * 128u * 32u];   // conv1 out  [B][128][128][32]  64 MB
__device__ float g_c2[32u * 64u * 64u * 64u];     // conv2 out  [B][64][64][64]    32 MB
__device__ float g_part[1024u * 32u * 128u];      // FC1 split-K partials          16 MB
__device__ float g_fc1[32 * 128];                 // FC1 raw sums (pre-bias/relu)
__device__ float g_theta[32 * 6];                 // theta

// ---------------- packed f32x2 helpers ----------------
__device__ __forceinline__ unsigned long long pack2(float x, float y) {
    unsigned long long r;
    asm("mov.b64 %0, {%1, %2};" : "=l"(r) : "f"(x), "f"(y));
    return r;
}
__device__ __forceinline__ void unpack2(unsigned long long v, float &lo, float &hi) {
    asm("mov.b64 {%0, %1}, %2;" : "=f"(lo), "=f"(hi) : "l"(v));
}
__device__ __forceinline__ unsigned long long ffma2(unsigned long long a,
                                                    unsigned long long b,
                                                    unsigned long long c) {
    unsigned long long d;
    asm("fma.rn.f32x2 %0, %1, %2, %3;" : "=l"(d) : "l"(a), "l"(b), "l"(c));
    return d;
}

// ---------------- conv1: [B,256,256,3] -> relu -> [B,128,128,32], stride 2, SAME(pad_lo=0) ----------------
__global__ void __launch_bounds__(128) conv1_k(const float* __restrict__ in,
                                               const float* __restrict__ k1,
                                               const float* __restrict__ b1) {
    __shared__ float ws[864];   // [tap(9)][ci(3)][co(32)]
    __shared__ float bs[32];
    int tid = threadIdx.x;
    for (int i = tid; i < 864; i += 128) ws[i] = k1[i];
    if (tid < 32) bs[tid] = b1[tid];
    __syncthreads();

    int idx = blockIdx.x * 128 + tid;          // b*16384 + oy*128 + ox
    int ox = idx & 127;
    int oy = (idx >> 7) & 127;
    int b  = idx >> 14;

    unsigned long long acc[16];
#pragma unroll
    for (int k = 0; k < 16; k++) acc[k] = pack2(bs[2 * k], bs[2 * k + 1]);

#pragma unroll
    for (int ky = 0; ky < 3; ky++) {
        int iy = 2 * oy + ky;
        if (iy >= 256) continue;
#pragma unroll
        for (int kx = 0; kx < 3; kx++) {
            int ix = 2 * ox + kx;
            if (ix >= 256) continue;
            const float* p = in + ((size_t)(b * 256 + iy) * 256 + ix) * 3;
#pragma unroll
            for (int ci = 0; ci < 3; ci++) {
                float v = p[ci];
                unsigned long long vv = pack2(v, v);
                const ulonglong2* wp =
                    (const ulonglong2*)(ws + ((ky * 3 + kx) * 3 + ci) * 32);
#pragma unroll
                for (int q = 0; q < 8; q++) {
                    ulonglong2 wv = wp[q];
                    acc[2 * q]     = ffma2(vv, wv.x, acc[2 * q]);
                    acc[2 * q + 1] = ffma2(vv, wv.y, acc[2 * q + 1]);
                }
            }
        }
    }

    float* o = g_c1 + (size_t)idx * 32;
#pragma unroll
    for (int q = 0; q < 8; q++) {
        float a0, a1, a2, a3;
        unpack2(acc[2 * q], a0, a1);
        unpack2(acc[2 * q + 1], a2, a3);
        float4 v = make_float4(fmaxf(a0, 0.f), fmaxf(a1, 0.f),
                               fmaxf(a2, 0.f), fmaxf(a3, 0.f));
        ((float4*)o)[q] = v;
    }
}

// ---------------- conv2: [B,128,128,32] -> relu -> [B,64,64,64], stride 2, SAME(pad_lo=0) ----------------
__global__ void __launch_bounds__(128) conv2_k(const float* __restrict__ k2,
                                               const float* __restrict__ b2) {
    __shared__ float ws[2048];  // weights for one tap: [ci(32)][co(64)]
    int tid = threadIdx.x;
    int idx = blockIdx.x * 128 + tid;          // b*4096 + oy*64 + ox
    int ox = idx & 63;
    int oy = (idx >> 6) & 63;
    int b  = idx >> 12;

    unsigned long long acc[32];
#pragma unroll
    for (int k = 0; k < 32; k++) acc[k] = pack2(b2[2 * k], b2[2 * k + 1]);

    for (int tap = 0; tap < 9; tap++) {
        __syncthreads();
        for (int i = tid; i < 2048; i += 128) ws[i] = k2[tap * 2048 + i];
        __syncthreads();

        int ky = tap / 3, kx = tap % 3;
        int iy = 2 * oy + ky;
        int ix = 2 * ox + kx;
        if (iy < 128 && ix < 128) {
            const float* p = g_c1 + ((size_t)(b * 128 + iy) * 128 + ix) * 32;
            for (int ci = 0; ci < 32; ci++) {
                float v = p[ci];
                unsigned long long vv = pack2(v, v);
                const ulonglong2* wp = (const ulonglong2*)(ws + ci * 64);
#pragma unroll
                for (int q = 0; q < 16; q++) {
                    ulonglong2 wv = wp[q];
                    acc[2 * q]     = ffma2(vv, wv.x, acc[2 * q]);
                    acc[2 * q + 1] = ffma2(vv, wv.y, acc[2 * q + 1]);
                }
            }
        }
    }

    float* o = g_c2 + (size_t)idx * 64;
#pragma unroll
    for (int q = 0; q < 16; q++) {
        float a0, a1, a2, a3;
        unpack2(acc[2 * q], a0, a1);
        unpack2(acc[2 * q + 1], a2, a3);
        float4 v = make_float4(fmaxf(a0, 0.f), fmaxf(a1, 0.f),
                               fmaxf(a2, 0.f), fmaxf(a3, 0.f));
        ((float4*)o)[q] = v;
    }
}

// ---------------- FC1 split-K: y[b][j] += sum_i x[b][i] * w1[i][j] ----------------
// Block = 128 threads (one per output column j), handles CH=256 rows of i.
__global__ void __launch_bounds__(128) fc1_k(const float* __restrict__ w1) {
    __shared__ float xs[256 * 36];  // [i][b] transposed, padded to 36 for LDS.128 alignment
    int tid = threadIdx.x;
    int i0  = blockIdx.x * 256;

    for (int b = 0; b < 32; b++) {
        const float* xb = g_c2 + (size_t)b * 262144 + i0;
        for (int i = tid; i < 256; i += 128) xs[i * 36 + b] = xb[i];
    }
    __syncthreads();

    unsigned long long acc[16];
#pragma unroll
    for (int k = 0; k < 16; k++) acc[k] = 0ull;

    int j = tid;
    const float* wp = w1 + (size_t)i0 * 128 + j;
    for (int i = 0; i < 256; i++) {
        float w = wp[(size_t)i * 128];
        unsigned long long ww = pack2(w, w);
        const ulonglong2* xp = (const ulonglong2*)(xs + i * 36);
#pragma unroll
        for (int q = 0; q < 8; q++) {
            ulonglong2 xv = xp[q];
            acc[2 * q]     = ffma2(xv.x, ww, acc[2 * q]);      // batches (4q, 4q+1)
            acc[2 * q + 1] = ffma2(xv.y, ww, acc[2 * q + 1]);  // batches (4q+2, 4q+3)
        }
    }

    float* P = g_part + (size_t)blockIdx.x * 4096 + j;
#pragma unroll
    for (int k = 0; k < 16; k++) {
        float lo, hi;
        unpack2(acc[k], lo, hi);
        P[(2 * k) * 128]     = lo;   // batch 2k
        P[(2 * k + 1) * 128] = hi;   // batch 2k+1
    }
}

// ---------------- reduce 1024 partials -> g_fc1 ----------------
__global__ void __launch_bounds__(128) reduce_k() {
    int t = blockIdx.x * 128 + threadIdx.x;  // 0..4095  (= b*128 + j)
    float s0 = 0.f, s1 = 0.f, s2 = 0.f, s3 = 0.f;
    for (int c = 0; c < 1024; c += 4) {
        s0 += g_part[(size_t)(c + 0) * 4096 + t];
        s1 += g_part[(size_t)(c + 1) * 4096 + t];
        s2 += g_part[(size_t)(c + 2) * 4096 + t];
        s3 += g_part[(size_t)(c + 3) * 4096 + t];
    }
    g_fc1[t] = (s0 + s1) + (s2 + s3);
}

// ---------------- FC2: theta[b][k] = d2[k] + sum_j relu(fc1[b][j]+d1[j]) * w2[j][k] ----------------
__global__ void fc2_k(const float* __restrict__ d1,
                      const float* __restrict__ w2,
                      const float* __restrict__ d2) {
    int t = threadIdx.x;
    if (t < 192) {
        int b = t / 6, k = t % 6;
        float s = d2[k];
        for (int j = 0; j < 128; j++) {
            float xv = fmaxf(g_fc1[b * 128 + j] + d1[j], 0.f);
            s += xv * w2[j * 6 + k];
        }
        g_theta[t] = s;
    }
}

// ---------------- bilinear grid sample, zero padding (GridSampler2D align_corners=False) ----------------
__global__ void __launch_bounds__(256) sample_k(const float* __restrict__ img,
                                                float* __restrict__ out) {
    int idx = blockIdx.x * 256 + threadIdx.x;  // b*65536 + y*256 + x
    int x = idx & 255;
    int y = (idx >> 8) & 255;
    int b = idx >> 16;

    const float* t = g_theta + b * 6;
    float X = (2.f * x + 1.f) * (1.f / 256.f) - 1.f;
    float Y = (2.f * y + 1.f) * (1.f / 256.f) - 1.f;
    float gx = t[0] * X + t[1] * Y + t[2];
    float gy = t[3] * X + t[4] * Y + t[5];
    float px = (gx + 1.f) * 128.f - 0.5f;
    float py = (gy + 1.f) * 128.f - 0.5f;

    float x0f = floorf(px), y0f = floorf(py);
    float wx1 = px - x0f, wx0 = 1.f - wx1;
    float wy1 = py - y0f, wy0 = 1.f - wy1;
    int x0 = (int)x0f, y0 = (int)y0f;

    const float* base = img + (size_t)b * 256 * 256 * 3;
    float r = 0.f, g = 0.f, bl = 0.f;

#pragma unroll
    for (int c = 0; c < 4; c++) {
        int yi = y0 + (c >> 1);
        int xi = x0 + (c & 1);
        float wgt = ((c >> 1) ? wy1 : wy0) * ((c & 1) ? wx1 : wx0);
        if (xi >= 0 && xi < 256 && yi >= 0 && yi < 256) {
            const float* p = base + ((size_t)yi * 256 + xi) * 3;
            r  += p[0] * wgt;
            g  += p[1] * wgt;
            bl += p[2] * wgt;
        }
    }

    float* o = out + (size_t)idx * 3;
    o[0] = r; o[1] = g; o[2] = bl;
}

// ---------------- launch ----------------
extern "C" void kernel_launch(void* const* d_in, const int* in_sizes, int n_in,
                              void* d_out, int out_size) {
    const float* inputs = (const float*)d_in[0];
    const float* k1 = (const float*)d_in[1];
    const float* b1 = (const float*)d_in[2];
    const float* k2 = (const float*)d_in[3];
    const float* b2 = (const float*)d_in[4];
    const float* w1 = (const float*)d_in[5];
    const float* d1 = (const float*)d_in[6];
    const float* w2 = (const float*)d_in[7];
    const float* d2 = (const float*)d_in[8];
    float* out = (float*)d_out;

    conv1_k<<<4096, 128>>>(inputs, k1, b1);    // 524288 threads
    conv2_k<<<1024, 128>>>(k2, b2);            // 131072 threads
    fc1_k<<<1024, 128>>>(w1);                  // split-K over 1024 chunks
    reduce_k<<<32, 128>>>();
    fc2_k<<<1, 192>>>(d1, w2, d2);
    sample_k<<<8192, 256>>>(inputs, out);      // 2097152 threads
}

// round 6
// speedup vs baseline: 1.2848x; 1.2848x over previous
#include <cuda_runtime.h>
#include <cstdint>

// ---------------- scratch (device globals; no allocations) ----------------
__device__ float g_c1[32u * 128u * 128u * 32u];   // conv1 out  [B][128][128][32]  64 MB
__device__ float g_c2[32u * 64u * 64u * 64u];     // conv2 out  [B][64][64][64]    32 MB
__device__ float g_part[1024u * 32u * 128u];      // FC1 split-K partials          16 MB
__device__ float g_part2[16u * 32u * 128u];       // second-stage partials
__device__ float g_fc1[32 * 128];                 // FC1 raw sums (pre-bias/relu)
__device__ float g_theta[32 * 6];                 // theta

// ---------------- packed f32x2 helpers ----------------
__device__ __forceinline__ unsigned long long pack2(float x, float y) {
    unsigned long long r;
    asm("mov.b64 %0, {%1, %2};" : "=l"(r) : "f"(x), "f"(y));
    return r;
}
__device__ __forceinline__ void unpack2(unsigned long long v, float &lo, float &hi) {
    asm("mov.b64 {%0, %1}, %2;" : "=f"(lo), "=f"(hi) : "l"(v));
}
__device__ __forceinline__ unsigned long long ffma2(unsigned long long a,
                                                    unsigned long long b,
                                                    unsigned long long c) {
    unsigned long long d;
    asm("fma.rn.f32x2 %0, %1, %2, %3;" : "=l"(d) : "l"(a), "l"(b), "l"(c));
    return d;
}

// ============================================================================
// conv1: [B,256,256,3] -> relu -> [B,128,128,32], stride 2, SAME (pad_lo=0)
// 2 pixels per thread; weights in smem; LDS:FFMA2 = 8:32 = 1:4.
// ============================================================================
__global__ void __launch_bounds__(128) conv1_k(const float* __restrict__ in,
                                               const float* __restrict__ k1,
                                               const float* __restrict__ b1) {
    __shared__ float ws[864];   // [tap(9)][ci(3)][co(32)]
    __shared__ float bs[32];
    int tid = threadIdx.x;
    for (int i = tid; i < 864; i += 128) ws[i] = k1[i];
    if (tid < 32) bs[tid] = b1[tid];
    __syncthreads();

    int pxA = blockIdx.x * 256 + tid;          // b*16384 + oy*128 + ox
    int pxB = pxA + 128;

    int oxA = pxA & 127, oyA = (pxA >> 7) & 127, bA = pxA >> 14;
    int oxB = pxB & 127, oyB = (pxB >> 7) & 127, bB = pxB >> 14;

    unsigned long long accA[16], accB[16];
#pragma unroll
    for (int k = 0; k < 16; k++) {
        unsigned long long bb = pack2(bs[2 * k], bs[2 * k + 1]);
        accA[k] = bb;
        accB[k] = bb;
    }

#pragma unroll
    for (int ky = 0; ky < 3; ky++) {
#pragma unroll
        for (int kx = 0; kx < 3; kx++) {
            int iyA = 2 * oyA + ky, ixA = 2 * oxA + kx;
            int iyB = 2 * oyB + ky, ixB = 2 * oxB + kx;
            bool vA = (iyA < 256) & (ixA < 256);
            bool vB = (iyB < 256) & (ixB < 256);
            const float* pA = in + ((size_t)(bA * 256 + iyA) * 256 + ixA) * 3;
            const float* pB = in + ((size_t)(bB * 256 + iyB) * 256 + ixB) * 3;
#pragma unroll
            for (int ci = 0; ci < 3; ci++) {
                float a = vA ? pA[ci] : 0.f;
                float b = vB ? pB[ci] : 0.f;
                unsigned long long va = pack2(a, a);
                unsigned long long vb = pack2(b, b);
                const ulonglong2* wp =
                    (const ulonglong2*)(ws + ((ky * 3 + kx) * 3 + ci) * 32);
#pragma unroll
                for (int q = 0; q < 8; q++) {
                    ulonglong2 wv = wp[q];
                    accA[2 * q]     = ffma2(va, wv.x, accA[2 * q]);
                    accA[2 * q + 1] = ffma2(va, wv.y, accA[2 * q + 1]);
                    accB[2 * q]     = ffma2(vb, wv.x, accB[2 * q]);
                    accB[2 * q + 1] = ffma2(vb, wv.y, accB[2 * q + 1]);
                }
            }
        }
    }

    float* oA = g_c1 + (size_t)pxA * 32;
    float* oB = g_c1 + (size_t)pxB * 32;
#pragma unroll
    for (int q = 0; q < 8; q++) {
        float a0, a1, a2, a3;
        unpack2(accA[2 * q], a0, a1);
        unpack2(accA[2 * q + 1], a2, a3);
        ((float4*)oA)[q] = make_float4(fmaxf(a0, 0.f), fmaxf(a1, 0.f),
                                       fmaxf(a2, 0.f), fmaxf(a3, 0.f));
        unpack2(accB[2 * q], a0, a1);
        unpack2(accB[2 * q + 1], a2, a3);
        ((float4*)oB)[q] = make_float4(fmaxf(a0, 0.f), fmaxf(a1, 0.f),
                                       fmaxf(a2, 0.f), fmaxf(a3, 0.f));
    }
}

// ============================================================================
// conv2: [B,128,128,32] -> relu -> [B,64,64,64], stride 2, SAME (pad_lo=0)
// Grid (512 pixel-blocks, 2 co-halves). 2 pixels x 32 co per thread.
// All 9 taps' weights for the co-half staged ONCE in smem (36 KB), no per-tap
// syncs. float4 input loads. LDS:FFMA2 = 8:32 = 1:4.
// ============================================================================
__global__ void __launch_bounds__(128) conv2_k(const float* __restrict__ k2,
                                               const float* __restrict__ b2) {
    __shared__ float ws[9 * 32 * 32];   // [tap][ci][co-half(32)]
    int tid = threadIdx.x;
    int h = blockIdx.y;                 // co half: co in [h*32, h*32+32)

    for (int u = tid; u < 9216; u += 128) {
        int tap = u >> 10;
        int ci  = (u >> 5) & 31;
        int c   = u & 31;
        ws[u] = k2[(tap * 32 + ci) * 64 + h * 32 + c];
    }
    __syncthreads();

    int pxA = blockIdx.x * 256 + tid;   // b*4096 + oy*64 + ox
    int pxB = pxA + 128;
    int oxA = pxA & 63, oyA = (pxA >> 6) & 63, bA = pxA >> 12;
    int oxB = pxB & 63, oyB = (pxB >> 6) & 63, bB = pxB >> 12;

    unsigned long long accA[16], accB[16];
#pragma unroll
    for (int k = 0; k < 16; k++) {
        unsigned long long bb = pack2(b2[h * 32 + 2 * k], b2[h * 32 + 2 * k + 1]);
        accA[k] = bb;
        accB[k] = bb;
    }

#pragma unroll 1
    for (int tap = 0; tap < 9; tap++) {
        int ky = tap / 3, kx = tap % 3;
        int iyA = 2 * oyA + ky, ixA = 2 * oxA + kx;
        int iyB = 2 * oyB + ky, ixB = 2 * oxB + kx;
        bool vA = (iyA < 128) & (ixA < 128);
        bool vB = (iyB < 128) & (ixB < 128);
        const float4* pA = (const float4*)(g_c1 + ((size_t)(bA * 128 + iyA) * 128 + ixA) * 32);
        const float4* pB = (const float4*)(g_c1 + ((size_t)(bB * 128 + iyB) * 128 + ixB) * 32);
        const float* wtap = ws + tap * 1024;

#pragma unroll 2
        for (int c4 = 0; c4 < 8; c4++) {
            float4 fa = vA ? pA[c4] : make_float4(0.f, 0.f, 0.f, 0.f);
            float4 fb = vB ? pB[c4] : make_float4(0.f, 0.f, 0.f, 0.f);
            float ea[4] = {fa.x, fa.y, fa.z, fa.w};
            float eb[4] = {fb.x, fb.y, fb.z, fb.w};
#pragma unroll
            for (int s = 0; s < 4; s++) {
                unsigned long long va = pack2(ea[s], ea[s]);
                unsigned long long vb = pack2(eb[s], eb[s]);
                const ulonglong2* wp = (const ulonglong2*)(wtap + (c4 * 4 + s) * 32);
#pragma unroll
                for (int q = 0; q < 8; q++) {
                    ulonglong2 wv = wp[q];
                    accA[2 * q]     = ffma2(va, wv.x, accA[2 * q]);
                    accA[2 * q + 1] = ffma2(va, wv.y, accA[2 * q + 1]);
                    accB[2 * q]     = ffma2(vb, wv.x, accB[2 * q]);
                    accB[2 * q + 1] = ffma2(vb, wv.y, accB[2 * q + 1]);
                }
            }
        }
    }

    float* oA = g_c2 + (size_t)pxA * 64 + h * 32;
    float* oB = g_c2 + (size_t)pxB * 64 + h * 32;
#pragma unroll
    for (int q = 0; q < 8; q++) {
        float a0, a1, a2, a3;
        unpack2(accA[2 * q], a0, a1);
        unpack2(accA[2 * q + 1], a2, a3);
        ((float4*)oA)[q] = make_float4(fmaxf(a0, 0.f), fmaxf(a1, 0.f),
                                       fmaxf(a2, 0.f), fmaxf(a3, 0.f));
        unpack2(accB[2 * q], a0, a1);
        unpack2(accB[2 * q + 1], a2, a3);
        ((float4*)oB)[q] = make_float4(fmaxf(a0, 0.f), fmaxf(a1, 0.f),
                                       fmaxf(a2, 0.f), fmaxf(a3, 0.f));
    }
}

// ============================================================================
// FC1 split-K: y[b][j] = sum_i x[b][i] * w1[i][j]
// Block = 64 threads; thread owns columns j and j+64; chunk = 256 i-rows.
// LDS:FFMA2 = 8:32 = 1:4.
// ============================================================================
__global__ void __launch_bounds__(64) fc1_k(const float* __restrict__ w1) {
    __shared__ float xs[256 * 36];  // [i][b], padded to 36 for 16B-aligned rows
    int tid = threadIdx.x;
    int i0  = blockIdx.x * 256;

    for (int b = 0; b < 32; b++) {
        const float* xb = g_c2 + (size_t)b * 262144 + i0;
        for (int i = tid; i < 256; i += 64) xs[i * 36 + b] = xb[i];
    }
    __syncthreads();

    unsigned long long accP[16], accQ[16];
#pragma unroll
    for (int k = 0; k < 16; k++) { accP[k] = 0ull; accQ[k] = 0ull; }

    int j = tid;
    const float* wp = w1 + (size_t)i0 * 128;
    for (int i = 0; i < 256; i++) {
        float w0  = wp[(size_t)i * 128 + j];
        float w1v = wp[(size_t)i * 128 + j + 64];
        unsigned long long ww0 = pack2(w0, w0);
        unsigned long long ww1 = pack2(w1v, w1v);
        const ulonglong2* xp = (const ulonglong2*)(xs + i * 36);
#pragma unroll
        for (int q = 0; q < 8; q++) {
            ulonglong2 xv = xp[q];
            accP[2 * q]     = ffma2(xv.x, ww0, accP[2 * q]);
            accP[2 * q + 1] = ffma2(xv.y, ww0, accP[2 * q + 1]);
            accQ[2 * q]     = ffma2(xv.x, ww1, accQ[2 * q]);
            accQ[2 * q + 1] = ffma2(xv.y, ww1, accQ[2 * q + 1]);
        }
    }

    float* P = g_part + (size_t)blockIdx.x * 4096;
#pragma unroll
    for (int k = 0; k < 16; k++) {
        float lo, hi;
        unpack2(accP[k], lo, hi);
        P[(2 * k) * 128 + j]     = lo;
        P[(2 * k + 1) * 128 + j] = hi;
        unpack2(accQ[k], lo, hi);
        P[(2 * k) * 128 + j + 64]     = lo;
        P[(2 * k + 1) * 128 + j + 64] = hi;
    }
}

// ---------------- reduce stage 1: 1024 chunks -> 16 partials ----------------
__global__ void __launch_bounds__(128) reduce1_k() {
    int bx = blockIdx.x;                 // (t-block 0..31, c-group 0..15)
    int t  = (bx & 31) * 128 + threadIdx.x;
    int c0 = (bx >> 5) * 64;
    float s0 = 0.f, s1 = 0.f, s2 = 0.f, s3 = 0.f;
    for (int c = 0; c < 64; c += 4) {
        s0 += g_part[(size_t)(c0 + c + 0) * 4096 + t];
        s1 += g_part[(size_t)(c0 + c + 1) * 4096 + t];
        s2 += g_part[(size_t)(c0 + c + 2) * 4096 + t];
        s3 += g_part[(size_t)(c0 + c + 3) * 4096 + t];
    }
    g_part2[(size_t)(bx >> 5) * 4096 + t] = (s0 + s1) + (s2 + s3);
}

// ---------------- reduce stage 2: 16 -> 1 ----------------
__global__ void __launch_bounds__(128) reduce2_k() {
    int t = blockIdx.x * 128 + threadIdx.x;  // 0..4095
    float s = 0.f;
#pragma unroll
    for (int g = 0; g < 16; g++) s += g_part2[(size_t)g * 4096 + t];
    g_fc1[t] = s;
}

// ---------------- FC2 ----------------
__global__ void fc2_k(const float* __restrict__ d1,
                      const float* __restrict__ w2,
                      const float* __restrict__ d2) {
    int t = threadIdx.x;
    if (t < 192) {
        int b = t / 6, k = t % 6;
        float s = d2[k];
        for (int j = 0; j < 128; j++) {
            float xv = fmaxf(g_fc1[b * 128 + j] + d1[j], 0.f);
            s += xv * w2[j * 6 + k];
        }
        g_theta[t] = s;
    }
}

// ---------------- bilinear grid sample, zero padding ----------------
__global__ void __launch_bounds__(256) sample_k(const float* __restrict__ img,
                                                float* __restrict__ out) {
    int idx = blockIdx.x * 256 + threadIdx.x;  // b*65536 + y*256 + x
    int x = idx & 255;
    int y = (idx >> 8) & 255;
    int b = idx >> 16;

    const float* t = g_theta + b * 6;
    float X = (2.f * x + 1.f) * (1.f / 256.f) - 1.f;
    float Y = (2.f * y + 1.f) * (1.f / 256.f) - 1.f;
    float gx = t[0] * X + t[1] * Y + t[2];
    float gy = t[3] * X + t[4] * Y + t[5];
    float px = (gx + 1.f) * 128.f - 0.5f;
    float py = (gy + 1.f) * 128.f - 0.5f;

    float x0f = floorf(px), y0f = floorf(py);
    float wx1 = px - x0f, wx0 = 1.f - wx1;
    float wy1 = py - y0f, wy0 = 1.f - wy1;
    int x0 = (int)x0f, y0 = (int)y0f;

    const float* base = img + (size_t)b * 256 * 256 * 3;
    float r = 0.f, g = 0.f, bl = 0.f;

#pragma unroll
    for (int c = 0; c < 4; c++) {
        int yi = y0 + (c >> 1);
        int xi = x0 + (c & 1);
        float wgt = ((c >> 1) ? wy1 : wy0) * ((c & 1) ? wx1 : wx0);
        if (xi >= 0 && xi < 256 && yi >= 0 && yi < 256) {
            const float* p = base + ((size_t)yi * 256 + xi) * 3;
            r  += p[0] * wgt;
            g  += p[1] * wgt;
            bl += p[2] * wgt;
        }
    }

    float* o = out + (size_t)idx * 3;
    o[0] = r; o[1] = g; o[2] = bl;
}

// ---------------- launch ----------------
extern "C" void kernel_launch(void* const* d_in, const int* in_sizes, int n_in,
                              void* d_out, int out_size) {
    const float* inputs = (const float*)d_in[0];
    const float* k1 = (const float*)d_in[1];
    const float* b1 = (const float*)d_in[2];
    const float* k2 = (const float*)d_in[3];
    const float* b2 = (const float*)d_in[4];
    const float* w1 = (const float*)d_in[5];
    const float* d1 = (const float*)d_in[6];
    const float* w2 = (const float*)d_in[7];
    const float* d2 = (const float*)d_in[8];
    float* out = (float*)d_out;

    conv1_k<<<2048, 128>>>(inputs, k1, b1);        // 2 px/thread
    conv2_k<<<dim3(512, 2), 128>>>(k2, b2);        // 2 px x 32 co per thread
    fc1_k<<<1024, 64>>>(w1);                       // 2 cols/thread split-K
    reduce1_k<<<512, 128>>>();
    reduce2_k<<<32, 128>>>();
    fc2_k<<<1, 192>>>(d1, w2, d2);
    sample_k<<<8192, 256>>>(inputs, out);
}

// round 7
// speedup vs baseline: 1.5869x; 1.2352x over previous
#include <cuda_runtime.h>
#include <cstdint>

// ---------------- scratch (device globals; no allocations) ----------------
__device__ float g_c1[32u * 128u * 128u * 32u];   // conv1 out  [B][128][128][32]  64 MB
__device__ float g_c2[32u * 64u * 64u * 64u];     // conv2 out  [B][64][64][64]    32 MB
__device__ float g_part[512u * 32u * 128u];       // FC1 split-K partials (512 chunks)
__device__ float g_part2[16u * 32u * 128u];       // second-stage partials
__device__ float g_fc1[32 * 128];                 // FC1 raw sums (pre-bias/relu)
__device__ float g_theta[32 * 6];                 // theta

// ---------------- packed f32x2 helpers ----------------
__device__ __forceinline__ unsigned long long pack2(float x, float y) {
    unsigned long long r;
    asm("mov.b64 %0, {%1, %2};" : "=l"(r) : "f"(x), "f"(y));
    return r;
}
__device__ __forceinline__ void unpack2(unsigned long long v, float &lo, float &hi) {
    asm("mov.b64 {%0, %1}, %2;" : "=f"(lo), "=f"(hi) : "l"(v));
}
__device__ __forceinline__ unsigned long long ffma2(unsigned long long a,
                                                    unsigned long long b,
                                                    unsigned long long c) {
    unsigned long long d;
    asm("fma.rn.f32x2 %0, %1, %2, %3;" : "=l"(d) : "l"(a), "l"(b), "l"(c));
    return d;
}

// ============================================================================
// conv1: [B,256,256,3] -> relu -> [B,128,128,32], stride 2, SAME (pad_lo=0)
// 2 pixels per thread; weights in smem; LDS:FFMA2 = 1:4.
// ============================================================================
__global__ void __launch_bounds__(128) conv1_k(const float* __restrict__ in,
                                               const float* __restrict__ k1,
                                               const float* __restrict__ b1) {
    __shared__ float ws[864];   // [tap(9)][ci(3)][co(32)]
    __shared__ float bs[32];
    int tid = threadIdx.x;
    for (int i = tid; i < 864; i += 128) ws[i] = k1[i];
    if (tid < 32) bs[tid] = b1[tid];
    __syncthreads();

    int pxA = blockIdx.x * 256 + tid;          // b*16384 + oy*128 + ox
    int pxB = pxA + 128;

    int oxA = pxA & 127, oyA = (pxA >> 7) & 127, bA = pxA >> 14;
    int oxB = pxB & 127, oyB = (pxB >> 7) & 127, bB = pxB >> 14;

    unsigned long long accA[16], accB[16];
#pragma unroll
    for (int k = 0; k < 16; k++) {
        unsigned long long bb = pack2(bs[2 * k], bs[2 * k + 1]);
        accA[k] = bb;
        accB[k] = bb;
    }

#pragma unroll
    for (int ky = 0; ky < 3; ky++) {
#pragma unroll
        for (int kx = 0; kx < 3; kx++) {
            int iyA = 2 * oyA + ky, ixA = 2 * oxA + kx;
            int iyB = 2 * oyB + ky, ixB = 2 * oxB + kx;
            bool vA = (iyA < 256) & (ixA < 256);
            bool vB = (iyB < 256) & (ixB < 256);
            const float* pA = in + ((size_t)(bA * 256 + iyA) * 256 + ixA) * 3;
            const float* pB = in + ((size_t)(bB * 256 + iyB) * 256 + ixB) * 3;
            // hoist all 6 loads
            float a0 = vA ? pA[0] : 0.f;
            float a1 = vA ? pA[1] : 0.f;
            float a2 = vA ? pA[2] : 0.f;
            float bb0 = vB ? pB[0] : 0.f;
            float bb1 = vB ? pB[1] : 0.f;
            float bb2 = vB ? pB[2] : 0.f;
            float ea[3] = {a0, a1, a2};
            float eb[3] = {bb0, bb1, bb2};
#pragma unroll
            for (int ci = 0; ci < 3; ci++) {
                unsigned long long va = pack2(ea[ci], ea[ci]);
                unsigned long long vb = pack2(eb[ci], eb[ci]);
                const ulonglong2* wp =
                    (const ulonglong2*)(ws + ((ky * 3 + kx) * 3 + ci) * 32);
#pragma unroll
                for (int q = 0; q < 8; q++) {
                    ulonglong2 wv = wp[q];
                    accA[2 * q]     = ffma2(va, wv.x, accA[2 * q]);
                    accA[2 * q + 1] = ffma2(va, wv.y, accA[2 * q + 1]);
                    accB[2 * q]     = ffma2(vb, wv.x, accB[2 * q]);
                    accB[2 * q + 1] = ffma2(vb, wv.y, accB[2 * q + 1]);
                }
            }
        }
    }

    float* oA = g_c1 + (size_t)pxA * 32;
    float* oB = g_c1 + (size_t)pxB * 32;
#pragma unroll
    for (int q = 0; q < 8; q++) {
        float a0, a1, a2, a3;
        unpack2(accA[2 * q], a0, a1);
        unpack2(accA[2 * q + 1], a2, a3);
        ((float4*)oA)[q] = make_float4(fmaxf(a0, 0.f), fmaxf(a1, 0.f),
                                       fmaxf(a2, 0.f), fmaxf(a3, 0.f));
        unpack2(accB[2 * q], a0, a1);
        unpack2(accB[2 * q + 1], a2, a3);
        ((float4*)oB)[q] = make_float4(fmaxf(a0, 0.f), fmaxf(a1, 0.f),
                                       fmaxf(a2, 0.f), fmaxf(a3, 0.f));
    }
}

// ============================================================================
// conv2: [B,128,128,32] -> relu -> [B,64,64,64], stride 2, SAME (pad_lo=0)
// Grid (512 pixel-blocks, 2 co-halves). 2 pixels x 32 co per thread.
// All 9 taps' weights for the co-half staged ONCE in smem (36 KB).
// Per tap: ALL 16 float4 input loads hoisted (MLP=16/thread), then fully
// unrolled compute. LDS:FFMA2 = 1:4.
// ============================================================================
__global__ void __launch_bounds__(128, 3) conv2_k(const float* __restrict__ k2,
                                                  const float* __restrict__ b2) {
    __shared__ float ws[9 * 32 * 32];   // [tap][ci][co-half(32)]
    int tid = threadIdx.x;
    int h = blockIdx.y;                 // co half: co in [h*32, h*32+32)

    for (int u = tid; u < 9216; u += 128) {
        int tap = u >> 10;
        int ci  = (u >> 5) & 31;
        int c   = u & 31;
        ws[u] = k2[(tap * 32 + ci) * 64 + h * 32 + c];
    }
    __syncthreads();

    int pxA = blockIdx.x * 256 + tid;   // b*4096 + oy*64 + ox
    int pxB = pxA + 128;
    int oxA = pxA & 63, oyA = (pxA >> 6) & 63, bA = pxA >> 12;
    int oxB = pxB & 63, oyB = (pxB >> 6) & 63, bB = pxB >> 12;

    unsigned long long accA[16], accB[16];
#pragma unroll
    for (int k = 0; k < 16; k++) {
        unsigned long long bb = pack2(b2[h * 32 + 2 * k], b2[h * 32 + 2 * k + 1]);
        accA[k] = bb;
        accB[k] = bb;
    }

    const float4 z4 = make_float4(0.f, 0.f, 0.f, 0.f);

#pragma unroll 1
    for (int tap = 0; tap < 9; tap++) {
        int ky = tap / 3, kx = tap % 3;
        int iyA = 2 * oyA + ky, ixA = 2 * oxA + kx;
        int iyB = 2 * oyB + ky, ixB = 2 * oxB + kx;
        bool vA = (iyA < 128) & (ixA < 128);
        bool vB = (iyB < 128) & (ixB < 128);
        const float4* pA = (const float4*)(g_c1 + ((size_t)(bA * 128 + iyA) * 128 + ixA) * 32);
        const float4* pB = (const float4*)(g_c1 + ((size_t)(bB * 128 + iyB) * 128 + ixB) * 32);

        // hoist ALL input loads for this tap (16 LDG.128 in flight)
        float4 ra[8], rb[8];
#pragma unroll
        for (int c4 = 0; c4 < 8; c4++) ra[c4] = vA ? pA[c4] : z4;
#pragma unroll
        for (int c4 = 0; c4 < 8; c4++) rb[c4] = vB ? pB[c4] : z4;

        const float* wtap = ws + tap * 1024;
#pragma unroll
        for (int c4 = 0; c4 < 8; c4++) {
            float ea[4] = {ra[c4].x, ra[c4].y, ra[c4].z, ra[c4].w};
            float eb[4] = {rb[c4].x, rb[c4].y, rb[c4].z, rb[c4].w};
#pragma unroll
            for (int s = 0; s < 4; s++) {
                unsigned long long va = pack2(ea[s], ea[s]);
                unsigned long long vb = pack2(eb[s], eb[s]);
                const ulonglong2* wp = (const ulonglong2*)(wtap + (c4 * 4 + s) * 32);
#pragma unroll
                for (int q = 0; q < 8; q++) {
                    ulonglong2 wv = wp[q];
                    accA[2 * q]     = ffma2(va, wv.x, accA[2 * q]);
                    accA[2 * q + 1] = ffma2(va, wv.y, accA[2 * q + 1]);
                    accB[2 * q]     = ffma2(vb, wv.x, accB[2 * q]);
                    accB[2 * q + 1] = ffma2(vb, wv.y, accB[2 * q + 1]);
                }
            }
        }
    }

    float* oA = g_c2 + (size_t)pxA * 64 + h * 32;
    float* oB = g_c2 + (size_t)pxB * 64 + h * 32;
#pragma unroll
    for (int q = 0; q < 8; q++) {
        float a0, a1, a2, a3;
        unpack2(accA[2 * q], a0, a1);
        unpack2(accA[2 * q + 1], a2, a3);
        ((float4*)oA)[q] = make_float4(fmaxf(a0, 0.f), fmaxf(a1, 0.f),
                                       fmaxf(a2, 0.f), fmaxf(a3, 0.f));
        unpack2(accB[2 * q], a0, a1);
        unpack2(accB[2 * q + 1], a2, a3);
        ((float4*)oB)[q] = make_float4(fmaxf(a0, 0.f), fmaxf(a1, 0.f),
                                       fmaxf(a2, 0.f), fmaxf(a3, 0.f));
    }
}

// ============================================================================
// FC1 split-K: y[b][j] = sum_i x[b][i] * w1[i][j]
// 512 blocks x 256 threads; chunk = 512 i-rows. Thread owns a COLUMN PAIR
// (j = 2*j2, j+1) via one float2 w-load, and an i-quarter (g = tid>>6, 128
// rows). LDS:FFMA2 = 8:32 = 1:4. Intra-block smem reduction of the 4
// i-quarters -> one partial chunk per block (512 chunks total).
// ============================================================================
__global__ void __launch_bounds__(256) fc1_k(const float* __restrict__ w1) {
    __shared__ float xs[512 * 36];  // [i][b] transposed; 73728 B; rows 16B-aligned
    int tid = threadIdx.x;
    int i0  = blockIdx.x * 512;

    for (int b = 0; b < 32; b++) {
        const float* xb = g_c2 + (size_t)b * 262144 + i0;
        for (int i = tid; i < 512; i += 256) xs[i * 36 + b] = xb[i];
    }
    __syncthreads();

    int j2 = tid & 63;          // column pair index: j = 2*j2
    int g  = tid >> 6;          // i-quarter 0..3

    unsigned long long accL[16], accR[16];
#pragma unroll
    for (int k = 0; k < 16; k++) { accL[k] = 0ull; accR[k] = 0ull; }

    const float* wp = w1 + (size_t)(i0 + g * 128) * 128 + 2 * j2;
#pragma unroll 4
    for (int i = 0; i < 128; i++) {
        float2 w = *(const float2*)(wp + (size_t)i * 128);
        unsigned long long wwL = pack2(w.x, w.x);
        unsigned long long wwR = pack2(w.y, w.y);
        const ulonglong2* xp = (const ulonglong2*)(xs + (g * 128 + i) * 36);
#pragma unroll
        for (int q = 0; q < 8; q++) {
            ulonglong2 xv = xp[q];
            accL[2 * q]     = ffma2(xv.x, wwL, accL[2 * q]);
            accL[2 * q + 1] = ffma2(xv.y, wwL, accL[2 * q + 1]);
            accR[2 * q]     = ffma2(xv.x, wwR, accR[2 * q]);
            accR[2 * q + 1] = ffma2(xv.y, wwR, accR[2 * q + 1]);
        }
    }
    __syncthreads();  // done reading xs; reuse it as reduction buffer

    // quarters g=1..3 dump their 64 values; g=0 threads reduce + store.
    // layout: xs[((g-1)*64 + j2)*66 + v], v = 4k + {L.lo, L.hi, R.lo, R.hi}
    if (g > 0) {
        float* dst = xs + ((size_t)(g - 1) * 64 + j2) * 66;
#pragma unroll
        for (int k = 0; k < 16; k++) {
            float l0, l1, r0, r1;
            unpack2(accL[k], l0, l1);
            unpack2(accR[k], r0, r1);
            dst[4 * k + 0] = l0;
            dst[4 * k + 1] = l1;
            dst[4 * k + 2] = r0;
            dst[4 * k + 3] = r1;
        }
    }
    __syncthreads();
    if (g == 0) {
        float* P = g_part + (size_t)blockIdx.x * 4096;
#pragma unroll
        for (int k = 0; k < 16; k++) {
            float l0, l1, r0, r1;
            unpack2(accL[k], l0, l1);
            unpack2(accR[k], r0, r1);
#pragma unroll
            for (int G = 0; G < 3; G++) {
                const float* src = xs + ((size_t)G * 64 + j2) * 66 + 4 * k;
                l0 += src[0];
                l1 += src[1];
                r0 += src[2];
                r1 += src[3];
            }
            P[(2 * k) * 128 + 2 * j2]         = l0;   // batch 2k,   col j
            P[(2 * k + 1) * 128 + 2 * j2]     = l1;   // batch 2k+1, col j
            P[(2 * k) * 128 + 2 * j2 + 1]     = r0;   // batch 2k,   col j+1
            P[(2 * k + 1) * 128 + 2 * j2 + 1] = r1;   // batch 2k+1, col j+1
        }
    }
}

// ---------------- reduce stage 1: 512 chunks -> 16 partials ----------------
__global__ void __launch_bounds__(128) reduce1_k() {
    int bx = blockIdx.x;                 // (t-block 0..31, c-group 0..15)
    int t  = (bx & 31) * 128 + threadIdx.x;
    int c0 = (bx >> 5) * 32;
    float s0 = 0.f, s1 = 0.f, s2 = 0.f, s3 = 0.f;
    for (int c = 0; c < 32; c += 4) {
        s0 += g_part[(size_t)(c0 + c + 0) * 4096 + t];
        s1 += g_part[(size_t)(c0 + c + 1) * 4096 + t];
        s2 += g_part[(size_t)(c0 + c + 2) * 4096 + t];
        s3 += g_part[(size_t)(c0 + c + 3) * 4096 + t];
    }
    g_part2[(size_t)(bx >> 5) * 4096 + t] = (s0 + s1) + (s2 + s3);
}

// ---------------- reduce stage 2: 16 -> 1 ----------------
__global__ void __launch_bounds__(128) reduce2_k() {
    int t = blockIdx.x * 128 + threadIdx.x;  // 0..4095
    float s = 0.f;
#pragma unroll
    for (int g = 0; g < 16; g++) s += g_part2[(size_t)g * 4096 + t];
    g_fc1[t] = s;
}

// ---------------- FC2 ----------------
__global__ void fc2_k(const float* __restrict__ d1,
                      const float* __restrict__ w2,
                      const float* __restrict__ d2) {
    int t = threadIdx.x;
    if (t < 192) {
        int b = t / 6, k = t % 6;
        float s = d2[k];
        for (int j = 0; j < 128; j++) {
            float xv = fmaxf(g_fc1[b * 128 + j] + d1[j], 0.f);
            s += xv * w2[j * 6 + k];
        }
        g_theta[t] = s;
    }
}

// ---------------- bilinear grid sample, zero padding ----------------
__global__ void __launch_bounds__(256) sample_k(const float* __restrict__ img,
                                                float* __restrict__ out) {
    int idx = blockIdx.x * 256 + threadIdx.x;  // b*65536 + y*256 + x
    int x = idx & 255;
    int y = (idx >> 8) & 255;
    int b = idx >> 16;

    const float* t = g_theta + b * 6;
    float X = (2.f * x + 1.f) * (1.f / 256.f) - 1.f;
    float Y = (2.f * y + 1.f) * (1.f / 256.f) - 1.f;
    float gx = t[0] * X + t[1] * Y + t[2];
    float gy = t[3] * X + t[4] * Y + t[5];
    float px = (gx + 1.f) * 128.f - 0.5f;
    float py = (gy + 1.f) * 128.f - 0.5f;

    float x0f = floorf(px), y0f = floorf(py);
    float wx1 = px - x0f, wx0 = 1.f - wx1;
    float wy1 = py - y0f, wy0 = 1.f - wy1;
    int x0 = (int)x0f, y0 = (int)y0f;

    const float* base = img + (size_t)b * 256 * 256 * 3;
    float r = 0.f, g = 0.f, bl = 0.f;

#pragma unroll
    for (int c = 0; c < 4; c++) {
        int yi = y0 + (c >> 1);
        int xi = x0 + (c & 1);
        float wgt = ((c >> 1) ? wy1 : wy0) * ((c & 1) ? wx1 : wx0);
        if (xi >= 0 && xi < 256 && yi >= 0 && yi < 256) {
            const float* p = base + ((size_t)yi * 256 + xi) * 3;
            r  += p[0] * wgt;
            g  += p[1] * wgt;
            bl += p[2] * wgt;
        }
    }

    float* o = out + (size_t)idx * 3;
    o[0] = r; o[1] = g; o[2] = bl;
}

// ---------------- launch ----------------
extern "C" void kernel_launch(void* const* d_in, const int* in_sizes, int n_in,
                              void* d_out, int out_size) {
    const float* inputs = (const float*)d_in[0];
    const float* k1 = (const float*)d_in[1];
    const float* b1 = (const float*)d_in[2];
    const float* k2 = (const float*)d_in[3];
    const float* b2 = (const float*)d_in[4];
    const float* w1 = (const float*)d_in[5];
    const float* d1 = (const float*)d_in[6];
    const float* w2 = (const float*)d_in[7];
    const float* d2 = (const float*)d_in[8];
    float* out = (float*)d_out;

    conv1_k<<<2048, 128>>>(inputs, k1, b1);        // 2 px/thread
    conv2_k<<<dim3(512, 2), 128>>>(k2, b2);        // 2 px x 32 co, loads hoisted
    fc1_k<<<512, 256>>>(w1);                       // 512-row chunks, col-pair threads
    reduce1_k<<<512, 128>>>();
    reduce2_k<<<32, 128>>>();
    fc2_k<<<1, 192>>>(d1, w2, d2);
    sample_k<<<8192, 256>>>(inputs, out);
}

// round 12
// speedup vs baseline: 2.3384x; 1.4736x over previous
#include <cuda_runtime.h>
#include <cuda_bf16.h>
#include <cstdint>

// ---------------- scratch (device globals; no allocations) ----------------
__device__ __nv_bfloat16 g_c1h[32u * 128u * 128u * 32u];  // conv1 out hi  33.5 MB
__device__ __nv_bfloat16 g_c1l[32u * 128u * 128u * 32u];  // conv1 out lo  33.5 MB
__device__ __nv_bfloat16 g_k2h[10 * 64 * 32];             // k2 transposed hi [tap][co][ci]
__device__ __nv_bfloat16 g_k2l[10 * 64 * 32];             // k2 transposed lo
__device__ float g_c2[32u * 64u * 64u * 64u];             // conv2 out  [B][64][64][64] 32 MB
__device__ float g_part[512u * 32u * 128u];               // FC1 split-K partials
__device__ float g_part2[16u * 32u * 128u];               // second-stage partials
__device__ float g_fc1[32 * 128];                         // FC1 raw sums
__device__ float g_theta[32 * 6];                         // theta

// ---------------- packed f32x2 helpers ----------------
__device__ __forceinline__ unsigned long long pack2(float x, float y) {
    unsigned long long r;
    asm("mov.b64 %0, {%1, %2};" : "=l"(r) : "f"(x), "f"(y));
    return r;
}
__device__ __forceinline__ void unpack2(unsigned long long v, float &lo, float &hi) {
    asm("mov.b64 {%0, %1}, %2;" : "=f"(lo), "=f"(hi) : "l"(v));
}
__device__ __forceinline__ unsigned long long ffma2(unsigned long long a,
                                                    unsigned long long b,
                                                    unsigned long long c) {
    unsigned long long d;
    asm("fma.rn.f32x2 %0, %1, %2, %3;" : "=l"(d) : "l"(a), "l"(b), "l"(c));
    return d;
}

// ---------------- warp-MMA helpers (baseline PTX, sm_80+) ----------------
__device__ __forceinline__ uint32_t smem_u32(const void* p) {
    uint32_t a;
    asm("{ .reg .u64 t; cvta.to.shared.u64 t, %1; cvt.u32.u64 %0, t; }" : "=r"(a) : "l"(p));
    return a;
}
__device__ __forceinline__ void ldmx4(uint32_t* r, uint32_t addr) {
    asm volatile("ldmatrix.sync.aligned.m8n8.x4.shared.b16 {%0,%1,%2,%3}, [%4];"
                 : "=r"(r[0]), "=r"(r[1]), "=r"(r[2]), "=r"(r[3]) : "r"(addr));
}
__device__ __forceinline__ void mma16816(float* c, const uint32_t* a, const uint32_t* b) {
    asm volatile("mma.sync.aligned.m16n8k16.row.col.f32.bf16.bf16.f32 "
                 "{%0,%1,%2,%3}, {%4,%5,%6,%7}, {%8,%9}, {%0,%1,%2,%3};"
                 : "+f"(c[0]), "+f"(c[1]), "+f"(c[2]), "+f"(c[3])
                 : "r"(a[0]), "r"(a[1]), "r"(a[2]), "r"(a[3]), "r"(b[0]), "r"(b[1]));
}

// ============================================================================
// conv1: [B,256,256,3] -> relu -> bf16 hi/lo [B,128,128,32], stride 2, SAME
// ============================================================================
__global__ void __launch_bounds__(128) conv1_k(const float* __restrict__ in,
                                               const float* __restrict__ k1,
                                               const float* __restrict__ b1) {
    __shared__ float ws[864];
    __shared__ float bs[32];
    int tid = threadIdx.x;
    for (int i = tid; i < 864; i += 128) ws[i] = k1[i];
    if (tid < 32) bs[tid] = b1[tid];
    __syncthreads();

    int pxA = blockIdx.x * 256 + tid;
    int pxB = pxA + 128;
    int oxA = pxA & 127, oyA = (pxA >> 7) & 127, bA = pxA >> 14;
    int oxB = pxB & 127, oyB = (pxB >> 7) & 127, bB = pxB >> 14;

    unsigned long long accA[16], accB[16];
#pragma unroll
    for (int k = 0; k < 16; k++) {
        unsigned long long bb = pack2(bs[2 * k], bs[2 * k + 1]);
        accA[k] = bb;
        accB[k] = bb;
    }

#pragma unroll
    for (int ky = 0; ky < 3; ky++) {
#pragma unroll
        for (int kx = 0; kx < 3; kx++) {
            int iyA = 2 * oyA + ky, ixA = 2 * oxA + kx;
            int iyB = 2 * oyB + ky, ixB = 2 * oxB + kx;
            bool vA = (iyA < 256) & (ixA < 256);
            bool vB = (iyB < 256) & (ixB < 256);
            const float* pA = in + ((size_t)(bA * 256 + iyA) * 256 + ixA) * 3;
            const float* pB = in + ((size_t)(bB * 256 + iyB) * 256 + ixB) * 3;
            float ea[3], eb[3];
#pragma unroll
            for (int c = 0; c < 3; c++) ea[c] = vA ? pA[c] : 0.f;
#pragma unroll
            for (int c = 0; c < 3; c++) eb[c] = vB ? pB[c] : 0.f;
#pragma unroll
            for (int ci = 0; ci < 3; ci++) {
                unsigned long long va = pack2(ea[ci], ea[ci]);
                unsigned long long vb = pack2(eb[ci], eb[ci]);
                const ulonglong2* wp =
                    (const ulonglong2*)(ws + ((ky * 3 + kx) * 3 + ci) * 32);
#pragma unroll
                for (int q = 0; q < 8; q++) {
                    ulonglong2 wv = wp[q];
                    accA[2 * q]     = ffma2(va, wv.x, accA[2 * q]);
                    accA[2 * q + 1] = ffma2(va, wv.y, accA[2 * q + 1]);
                    accB[2 * q]     = ffma2(vb, wv.x, accB[2 * q]);
                    accB[2 * q + 1] = ffma2(vb, wv.y, accB[2 * q + 1]);
                }
            }
        }
    }

    // epilogue: relu, split to bf16 hi + lo, vectorized store
    __align__(16) __nv_bfloat16 hv[32], lv[32];
#pragma unroll
    for (int q = 0; q < 8; q++) {
        float r[4];
        unpack2(accA[2 * q], r[0], r[1]);
        unpack2(accA[2 * q + 1], r[2], r[3]);
#pragma unroll
        for (int i = 0; i < 4; i++) {
            float v = fmaxf(r[i], 0.f);
            __nv_bfloat16 h = __float2bfloat16_rn(v);
            hv[4 * q + i] = h;
            lv[4 * q + i] = __float2bfloat16_rn(v - __bfloat162float(h));
        }
    }
    uint4* dh = (uint4*)(g_c1h + (size_t)pxA * 32);
    uint4* dl = (uint4*)(g_c1l + (size_t)pxA * 32);
#pragma unroll
    for (int j = 0; j < 4; j++) { dh[j] = ((uint4*)hv)[j]; dl[j] = ((uint4*)lv)[j]; }

#pragma unroll
    for (int q = 0; q < 8; q++) {
        float r[4];
        unpack2(accB[2 * q], r[0], r[1]);
        unpack2(accB[2 * q + 1], r[2], r[3]);
#pragma unroll
        for (int i = 0; i < 4; i++) {
            float v = fmaxf(r[i], 0.f);
            __nv_bfloat16 h = __float2bfloat16_rn(v);
            hv[4 * q + i] = h;
            lv[4 * q + i] = __float2bfloat16_rn(v - __bfloat162float(h));
        }
    }
    dh = (uint4*)(g_c1h + (size_t)pxB * 32);
    dl = (uint4*)(g_c1l + (size_t)pxB * 32);
#pragma unroll
    for (int j = 0; j < 4; j++) { dh[j] = ((uint4*)hv)[j]; dl[j] = ((uint4*)lv)[j]; }
}

// ---------------- weight prep: k2 -> transposed bf16 hi/lo [tap][co][ci] ----------------
__global__ void wprep_k(const float* __restrict__ k2) {
    int t = blockIdx.x * 256 + threadIdx.x;   // 10 * 64 * 32 = 20480
    if (t < 20480) {
        int ci = t & 31, co = (t >> 5) & 63, tap = t >> 11;
        float w = (tap < 9) ? k2[(tap * 32 + ci) * 64 + co] : 0.f;
        __nv_bfloat16 h = __float2bfloat16_rn(w);
        g_k2h[t] = h;
        g_k2l[t] = __float2bfloat16_rn(w - __bfloat162float(h));
    }
}

__global__ void dummy_k() {}

// ============================================================================
// conv2 via warp-level bf16 MMA (m16n8k16), 2-term split hh+hl+lh.
// Block = 128 threads = 4 warps; output tile 128 px x 64 co; K = 9 taps x 32 ci.
// Per tap: stage A[128][32] hi/lo + B[64][32] hi/lo into smem with 40-elem
// pitch (80B row stride -> conflict-free ldmatrix). Warp w owns pixels
// [32w, 32w+32): 2 m-tiles x 8 n-tiles, acc f32 in registers.
// ============================================================================
__global__ void __launch_bounds__(128) conv2_mma(const float* __restrict__ b2) {
    __shared__ __align__(16) __nv_bfloat16 sA[2][128 * 40];  // [plane][row*40+col]
    __shared__ __align__(16) __nv_bfloat16 sB[2][64 * 40];

    int tid = threadIdx.x;
    int wid = tid >> 5;
    int lane = tid & 31;
    int b   = blockIdx.x >> 5;
    int oy0 = (blockIdx.x & 31) * 2;

    float acc[2][8][4];
#pragma unroll
    for (int mt = 0; mt < 2; mt++)
#pragma unroll
        for (int nt = 0; nt < 8; nt++)
#pragma unroll
            for (int i = 0; i < 4; i++) acc[mt][nt][i] = 0.f;

    const uint4 z4 = make_uint4(0, 0, 0, 0);

#pragma unroll 1
    for (int tap = 0; tap < 9; tap++) {
        int ky = tap / 3, kx = tap % 3;
        __syncthreads();   // previous tap's compute done before overwrite

        // ---- stage A: 1024 uint4 slots (2 planes x 128 rows x 4 vec) ----
#pragma unroll
        for (int j = 0; j < 8; j++) {
            int s = j * 128 + tid;
            int v = s & 3;
            int m = (s >> 2) & 127;
            int p = s >> 9;
            int row = m >> 6, ox = m & 63;
            int oy = oy0 + row;
            int iy = 2 * oy + ky, ix = 2 * ox + kx;
            uint4 val = z4;
            if (iy < 128 && ix < 128) {
                const __nv_bfloat16* src = (p ? g_c1l : g_c1h)
                    + ((size_t)(b * 128 + iy) * 128 + ix) * 32 + v * 8;
                val = *(const uint4*)src;
            }
            *(uint4*)(&sA[p][m * 40 + v * 8]) = val;
        }
        // ---- stage B: 512 uint4 slots (2 planes x 64 rows x 4 vec) ----
#pragma unroll
        for (int j = 0; j < 4; j++) {
            int s = j * 128 + tid;
            int v = s & 3;
            int n = (s >> 2) & 63;
            int p = s >> 8;
            const __nv_bfloat16* src = (p ? g_k2l : g_k2h)
                + ((size_t)tap * 64 + n) * 32 + v * 8;
            *(uint4*)(&sB[p][n * 40 + v * 8]) = *(const uint4*)src;
        }
        __syncthreads();

        // ---- compute: 2 ksubs x (2 m-tiles x 8 n-tiles x 3 splits) ----
#pragma unroll
        for (int ksub = 0; ksub < 2; ksub++) {
            // A fragments (hi & lo) for both m-tiles
            uint32_t aH[2][4], aL[2][4];
            {
                int rowf = (lane & 15);
                int colf = ksub * 16 + ((lane >> 4) << 3);
#pragma unroll
                for (int mt = 0; mt < 2; mt++) {
                    uint32_t off = (uint32_t)((wid * 32 + mt * 16 + rowf) * 40 + colf) * 2;
                    ldmx4(aH[mt], smem_u32(sA[0]) + off);
                    ldmx4(aL[mt], smem_u32(sA[1]) + off);
                }
            }
            // B fragments (hi & lo) for all 8 n-tiles (pairs via x4)
            uint32_t bH[8][2], bL[8][2];
            {
                int nf = ((lane >> 4) & 1) * 8 + (lane & 7);
                int kf = ksub * 16 + ((lane >> 3) & 1) * 8;
#pragma unroll
                for (int ntp = 0; ntp < 4; ntp++) {
                    uint32_t off = (uint32_t)((ntp * 16 + nf) * 40 + kf) * 2;
                    uint32_t r[4];
                    ldmx4(r, smem_u32(sB[0]) + off);
                    bH[2 * ntp][0] = r[0]; bH[2 * ntp][1] = r[1];
                    bH[2 * ntp + 1][0] = r[2]; bH[2 * ntp + 1][1] = r[3];
                    ldmx4(r, smem_u32(sB[1]) + off);
                    bL[2 * ntp][0] = r[0]; bL[2 * ntp][1] = r[1];
                    bL[2 * ntp + 1][0] = r[2]; bL[2 * ntp + 1][1] = r[3];
                }
            }
#pragma unroll
            for (int mt = 0; mt < 2; mt++)
#pragma unroll
                for (int nt = 0; nt < 8; nt++) {
                    mma16816(acc[mt][nt], aH[mt], bH[nt]);
                    mma16816(acc[mt][nt], aH[mt], bL[nt]);
                    mma16816(acc[mt][nt], aL[mt], bH[nt]);
                }
        }
    }

    // ---- epilogue: +bias, relu, store to g_c2 ----
#pragma unroll
    for (int mt = 0; mt < 2; mt++) {
        int r0 = wid * 32 + mt * 16 + (lane >> 2);
        int r1 = r0 + 8;
        int px0 = b * 4096 + (oy0 + (r0 >> 6)) * 64 + (r0 & 63);
        int px1 = b * 4096 + (oy0 + (r1 >> 6)) * 64 + (r1 & 63);
#pragma unroll
        for (int nt = 0; nt < 8; nt++) {
            int c = nt * 8 + (lane & 3) * 2;
            float bc0 = b2[c], bc1 = b2[c + 1];
            float2 v0, v1;
            v0.x = fmaxf(acc[mt][nt][0] + bc0, 0.f);
            v0.y = fmaxf(acc[mt][nt][1] + bc1, 0.f);
            v1.x = fmaxf(acc[mt][nt][2] + bc0, 0.f);
            v1.y = fmaxf(acc[mt][nt][3] + bc1, 0.f);
            *(float2*)(g_c2 + (size_t)px0 * 64 + c) = v0;
            *(float2*)(g_c2 + (size_t)px1 * 64 + c) = v1;
        }
    }
}

// ============================================================================
// FC1 split-K (fp32) — unchanged from best passing kernel
// ============================================================================
__global__ void __launch_bounds__(256) fc1_k(const float* __restrict__ w1) {
    __shared__ float xs[512 * 36];
    int tid = threadIdx.x;
    int i0  = blockIdx.x * 512;

    for (int b = 0; b < 32; b++) {
        const float* xb = g_c2 + (size_t)b * 262144 + i0;
        for (int i = tid; i < 512; i += 256) xs[i * 36 + b] = xb[i];
    }
    __syncthreads();

    int j2 = tid & 63;
    int g  = tid >> 6;

    unsigned long long accL[16], accR[16];
#pragma unroll
    for (int k = 0; k < 16; k++) { accL[k] = 0ull; accR[k] = 0ull; }

    const float* wp = w1 + (size_t)(i0 + g * 128) * 128 + 2 * j2;
#pragma unroll 4
    for (int i = 0; i < 128; i++) {
        float2 w = *(const float2*)(wp + (size_t)i * 128);
        unsigned long long wwL = pack2(w.x, w.x);
        unsigned long long wwR = pack2(w.y, w.y);
        const ulonglong2* xp = (const ulonglong2*)(xs + (g * 128 + i) * 36);
#pragma unroll
        for (int q = 0; q < 8; q++) {
            ulonglong2 xv = xp[q];
            accL[2 * q]     = ffma2(xv.x, wwL, accL[2 * q]);
            accL[2 * q + 1] = ffma2(xv.y, wwL, accL[2 * q + 1]);
            accR[2 * q]     = ffma2(xv.x, wwR, accR[2 * q]);
            accR[2 * q + 1] = ffma2(xv.y, wwR, accR[2 * q + 1]);
        }
    }
    __syncthreads();

    if (g > 0) {
        float* dst = xs + ((size_t)(g - 1) * 64 + j2) * 66;
#pragma unroll
        for (int k = 0; k < 16; k++) {
            float l0, l1, r0, r1;
            unpack2(accL[k], l0, l1);
            unpack2(accR[k], r0, r1);
            dst[4 * k + 0] = l0;
            dst[4 * k + 1] = l1;
            dst[4 * k + 2] = r0;
            dst[4 * k + 3] = r1;
        }
    }
    __syncthreads();
    if (g == 0) {
        float* P = g_part + (size_t)blockIdx.x * 4096;
#pragma unroll
        for (int k = 0; k < 16; k++) {
            float l0, l1, r0, r1;
            unpack2(accL[k], l0, l1);
            unpack2(accR[k], r0, r1);
#pragma unroll
            for (int G = 0; G < 3; G++) {
                const float* src = xs + ((size_t)G * 64 + j2) * 66 + 4 * k;
                l0 += src[0];
                l1 += src[1];
                r0 += src[2];
                r1 += src[3];
            }
            P[(2 * k) * 128 + 2 * j2]         = l0;
            P[(2 * k + 1) * 128 + 2 * j2]     = l1;
            P[(2 * k) * 128 + 2 * j2 + 1]     = r0;
            P[(2 * k + 1) * 128 + 2 * j2 + 1] = r1;
        }
    }
}

// ---------------- reduce stage 1: 512 chunks -> 16 partials ----------------
__global__ void __launch_bounds__(128) reduce1_k() {
    int bx = blockIdx.x;
    int t  = (bx & 31) * 128 + threadIdx.x;
    int c0 = (bx >> 5) * 32;
    float s0 = 0.f, s1 = 0.f, s2 = 0.f, s3 = 0.f;
    for (int c = 0; c < 32; c += 4) {
        s0 += g_part[(size_t)(c0 + c + 0) * 4096 + t];
        s1 += g_part[(size_t)(c0 + c + 1) * 4096 + t];
        s2 += g_part[(size_t)(c0 + c + 2) * 4096 + t];
        s3 += g_part[(size_t)(c0 + c + 3) * 4096 + t];
    }
    g_part2[(size_t)(bx >> 5) * 4096 + t] = (s0 + s1) + (s2 + s3);
}

// ---------------- reduce stage 2: 16 -> 1 ----------------
__global__ void __launch_bounds__(128) reduce2_k() {
    int t = blockIdx.x * 128 + threadIdx.x;
    float s = 0.f;
#pragma unroll
    for (int g = 0; g < 16; g++) s += g_part2[(size_t)g * 4096 + t];
    g_fc1[t] = s;
}

// ---------------- FC2 ----------------
__global__ void fc2_k(const float* __restrict__ d1,
                      const float* __restrict__ w2,
                      const float* __restrict__ d2) {
    int t = threadIdx.x;
    if (t < 192) {
        int b = t / 6, k = t % 6;
        float s = d2[k];
        for (int j = 0; j < 128; j++) {
            float xv = fmaxf(g_fc1[b * 128 + j] + d1[j], 0.f);
            s += xv * w2[j * 6 + k];
        }
        g_theta[t] = s;
    }
}

// ---------------- bilinear grid sample, zero padding ----------------
__global__ void __launch_bounds__(256) sample_k(const float* __restrict__ img,
                                                float* __restrict__ out) {
    int idx = blockIdx.x * 256 + threadIdx.x;
    int x = idx & 255;
    int y = (idx >> 8) & 255;
    int b = idx >> 16;

    const float* t = g_theta + b * 6;
    float X = (2.f * x + 1.f) * (1.f / 256.f) - 1.f;
    float Y = (2.f * y + 1.f) * (1.f / 256.f) - 1.f;
    float gx = t[0] * X + t[1] * Y + t[2];
    float gy = t[3] * X + t[4] * Y + t[5];
    float px = (gx + 1.f) * 128.f - 0.5f;
    float py = (gy + 1.f) * 128.f - 0.5f;

    float x0f = floorf(px), y0f = floorf(py);
    float wx1 = px - x0f, wx0 = 1.f - wx1;
    float wy1 = py - y0f, wy0 = 1.f - wy1;
    int x0 = (int)x0f, y0 = (int)y0f;

    const float* base = img + (size_t)b * 256 * 256 * 3;
    float r = 0.f, g = 0.f, bl = 0.f;

#pragma unroll
    for (int c = 0; c < 4; c++) {
        int yi = y0 + (c >> 1);
        int xi = x0 + (c & 1);
        float wgt = ((c >> 1) ? wy1 : wy0) * ((c & 1) ? wx1 : wx0);
        if (xi >= 0 && xi < 256 && yi >= 0 && yi < 256) {
            const float* p = base + ((size_t)yi * 256 + xi) * 3;
            r  += p[0] * wgt;
            g  += p[1] * wgt;
            bl += p[2] * wgt;
        }
    }

    float* o = out + (size_t)idx * 3;
    o[0] = r; o[1] = g; o[2] = bl;
}

// ---------------- launch ----------------
extern "C" void kernel_launch(void* const* d_in, const int* in_sizes, int n_in,
                              void* d_out, int out_size) {
    const float* inputs = (const float*)d_in[0];
    const float* k1 = (const float*)d_in[1];
    const float* b1 = (const float*)d_in[2];
    const float* k2 = (const float*)d_in[3];
    const float* b2 = (const float*)d_in[4];
    const float* w1 = (const float*)d_in[5];
    const float* d1 = (const float*)d_in[6];
    const float* w2 = (const float*)d_in[7];
    const float* d2 = (const float*)d_in[8];
    float* out = (float*)d_out;

    conv1_k<<<2048, 128>>>(inputs, k1, b1);     // slot 0
    wprep_k<<<80, 256>>>(k2);                   // slot 1
    dummy_k<<<1, 32>>>();                       // slot 2 (aligns conv2_mma to profiled slot 3)
    conv2_mma<<<1024, 128>>>(b2);               // slot 3  <- profiled
    fc1_k<<<512, 256>>>(w1);
    reduce1_k<<<512, 128>>>();
    reduce2_k<<<32, 128>>>();
    fc2_k<<<1, 192>>>(d1, w2, d2);
    sample_k<<<8192, 256>>>(inputs, out);
}

// round 15
// speedup vs baseline: 2.3953x; 1.0243x over previous
#include <cuda_runtime.h>
#include <cuda_bf16.h>
#include <cstdint>

// ---------------- scratch (device globals; no allocations) ----------------
__device__ __nv_bfloat16 g_c1h[32u * 128u * 128u * 32u];  // conv1 out hi  33.5 MB
__device__ __nv_bfloat16 g_c1l[32u * 128u * 128u * 32u];  // conv1 out lo  33.5 MB
__device__ __nv_bfloat16 g_k2h[10 * 64 * 32];             // k2 transposed hi [tap][co][ci]
__device__ __nv_bfloat16 g_k2l[10 * 64 * 32];             // k2 transposed lo
__device__ float g_c2[32u * 64u * 64u * 64u];             // conv2 out  [B][64][64][64] 32 MB
__device__ float g_part[512u * 32u * 128u];               // FC1 split-K partials
__device__ float g_part2[16u * 32u * 128u];               // second-stage partials
__device__ float g_fc1[32 * 128];                         // FC1 raw sums
__device__ float g_theta[32 * 6];                         // theta

// ---------------- packed f32x2 helpers ----------------
__device__ __forceinline__ unsigned long long pack2(float x, float y) {
    unsigned long long r;
    asm("mov.b64 %0, {%1, %2};" : "=l"(r) : "f"(x), "f"(y));
    return r;
}
__device__ __forceinline__ void unpack2(unsigned long long v, float &lo, float &hi) {
    asm("mov.b64 {%0, %1}, %2;" : "=f"(lo), "=f"(hi) : "l"(v));
}
__device__ __forceinline__ unsigned long long ffma2(unsigned long long a,
                                                    unsigned long long b,
                                                    unsigned long long c) {
    unsigned long long d;
    asm("fma.rn.f32x2 %0, %1, %2, %3;" : "=l"(d) : "l"(a), "l"(b), "l"(c));
    return d;
}

// ---------------- warp-MMA helpers (baseline PTX, sm_80+) ----------------
__device__ __forceinline__ uint32_t smem_u32(const void* p) {
    uint32_t a;
    asm("{ .reg .u64 t; cvta.to.shared.u64 t, %1; cvt.u32.u64 %0, t; }" : "=r"(a) : "l"(p));
    return a;
}
__device__ __forceinline__ void ldmx4(uint32_t* r, uint32_t addr) {
    asm volatile("ldmatrix.sync.aligned.m8n8.x4.shared.b16 {%0,%1,%2,%3}, [%4];"
                 : "=r"(r[0]), "=r"(r[1]), "=r"(r[2]), "=r"(r[3]) : "r"(addr));
}
__device__ __forceinline__ void ldmx4t(uint32_t* r, uint32_t addr) {
    asm volatile("ldmatrix.sync.aligned.m8n8.x4.trans.shared.b16 {%0,%1,%2,%3}, [%4];"
                 : "=r"(r[0]), "=r"(r[1]), "=r"(r[2]), "=r"(r[3]) : "r"(addr));
}
__device__ __forceinline__ void mma16816(float* c, const uint32_t* a, const uint32_t* b) {
    asm volatile("mma.sync.aligned.m16n8k16.row.col.f32.bf16.bf16.f32 "
                 "{%0,%1,%2,%3}, {%4,%5,%6,%7}, {%8,%9}, {%0,%1,%2,%3};"
                 : "+f"(c[0]), "+f"(c[1]), "+f"(c[2]), "+f"(c[3])
                 : "r"(a[0]), "r"(a[1]), "r"(a[2]), "r"(a[3]), "r"(b[0]), "r"(b[1]));
}

// ============================================================================
// conv1: [B,256,256,3] -> relu -> bf16 hi/lo [B,128,128,32], stride 2, SAME
// ============================================================================
__global__ void __launch_bounds__(128) conv1_k(const float* __restrict__ in,
                                               const float* __restrict__ k1,
                                               const float* __restrict__ b1) {
    __shared__ float ws[864];
    __shared__ float bs[32];
    int tid = threadIdx.x;
    for (int i = tid; i < 864; i += 128) ws[i] = k1[i];
    if (tid < 32) bs[tid] = b1[tid];
    __syncthreads();

    int pxA = blockIdx.x * 256 + tid;
    int pxB = pxA + 128;
    int oxA = pxA & 127, oyA = (pxA >> 7) & 127, bA = pxA >> 14;
    int oxB = pxB & 127, oyB = (pxB >> 7) & 127, bB = pxB >> 14;

    unsigned long long accA[16], accB[16];
#pragma unroll
    for (int k = 0; k < 16; k++) {
        unsigned long long bb = pack2(bs[2 * k], bs[2 * k + 1]);
        accA[k] = bb;
        accB[k] = bb;
    }

#pragma unroll
    for (int ky = 0; ky < 3; ky++) {
#pragma unroll
        for (int kx = 0; kx < 3; kx++) {
            int iyA = 2 * oyA + ky, ixA = 2 * oxA + kx;
            int iyB = 2 * oyB + ky, ixB = 2 * oxB + kx;
            bool vA = (iyA < 256) & (ixA < 256);
            bool vB = (iyB < 256) & (ixB < 256);
            const float* pA = in + ((size_t)(bA * 256 + iyA) * 256 + ixA) * 3;
            const float* pB = in + ((size_t)(bB * 256 + iyB) * 256 + ixB) * 3;
            float ea[3], eb[3];
#pragma unroll
            for (int c = 0; c < 3; c++) ea[c] = vA ? pA[c] : 0.f;
#pragma unroll
            for (int c = 0; c < 3; c++) eb[c] = vB ? pB[c] : 0.f;
#pragma unroll
            for (int ci = 0; ci < 3; ci++) {
                unsigned long long va = pack2(ea[ci], ea[ci]);
                unsigned long long vb = pack2(eb[ci], eb[ci]);
                const ulonglong2* wp =
                    (const ulonglong2*)(ws + ((ky * 3 + kx) * 3 + ci) * 32);
#pragma unroll
                for (int q = 0; q < 8; q++) {
                    ulonglong2 wv = wp[q];
                    accA[2 * q]     = ffma2(va, wv.x, accA[2 * q]);
                    accA[2 * q + 1] = ffma2(va, wv.y, accA[2 * q + 1]);
                    accB[2 * q]     = ffma2(vb, wv.x, accB[2 * q]);
                    accB[2 * q + 1] = ffma2(vb, wv.y, accB[2 * q + 1]);
                }
            }
        }
    }

    __align__(16) __nv_bfloat16 hv[32], lv[32];
#pragma unroll
    for (int q = 0; q < 8; q++) {
        float r[4];
        unpack2(accA[2 * q], r[0], r[1]);
        unpack2(accA[2 * q + 1], r[2], r[3]);
#pragma unroll
        for (int i = 0; i < 4; i++) {
            float v = fmaxf(r[i], 0.f);
            __nv_bfloat16 h = __float2bfloat16_rn(v);
            hv[4 * q + i] = h;
            lv[4 * q + i] = __float2bfloat16_rn(v - __bfloat162float(h));
        }
    }
    uint4* dh = (uint4*)(g_c1h + (size_t)pxA * 32);
    uint4* dl = (uint4*)(g_c1l + (size_t)pxA * 32);
#pragma unroll
    for (int j = 0; j < 4; j++) { dh[j] = ((uint4*)hv)[j]; dl[j] = ((uint4*)lv)[j]; }

#pragma unroll
    for (int q = 0; q < 8; q++) {
        float r[4];
        unpack2(accB[2 * q], r[0], r[1]);
        unpack2(accB[2 * q + 1], r[2], r[3]);
#pragma unroll
        for (int i = 0; i < 4; i++) {
            float v = fmaxf(r[i], 0.f);
            __nv_bfloat16 h = __float2bfloat16_rn(v);
            hv[4 * q + i] = h;
            lv[4 * q + i] = __float2bfloat16_rn(v - __bfloat162float(h));
        }
    }
    dh = (uint4*)(g_c1h + (size_t)pxB * 32);
    dl = (uint4*)(g_c1l + (size_t)pxB * 32);
#pragma unroll
    for (int j = 0; j < 4; j++) { dh[j] = ((uint4*)hv)[j]; dl[j] = ((uint4*)lv)[j]; }
}

// ---------------- weight prep: k2 -> transposed bf16 hi/lo [tap][co][ci] ----------------
__global__ void wprep_k(const float* __restrict__ k2) {
    int t = blockIdx.x * 256 + threadIdx.x;   // 10 * 64 * 32 = 20480
    if (t < 20480) {
        int ci = t & 31, co = (t >> 5) & 63, tap = t >> 11;
        float w = (tap < 9) ? k2[(tap * 32 + ci) * 64 + co] : 0.f;
        __nv_bfloat16 h = __float2bfloat16_rn(w);
        g_k2h[t] = h;
        g_k2l[t] = __float2bfloat16_rn(w - __bfloat162float(h));
    }
}

// ============================================================================
// conv2 via warp-level bf16 MMA (m16n8k16), 2-term split hh+hl+lh.
// (unchanged from 225us kernel)
// ============================================================================
__global__ void __launch_bounds__(128) conv2_mma(const float* __restrict__ b2) {
    __shared__ __align__(16) __nv_bfloat16 sA[2][128 * 40];
    __shared__ __align__(16) __nv_bfloat16 sB[2][64 * 40];

    int tid = threadIdx.x;
    int wid = tid >> 5;
    int lane = tid & 31;
    int b   = blockIdx.x >> 5;
    int oy0 = (blockIdx.x & 31) * 2;

    float acc[2][8][4];
#pragma unroll
    for (int mt = 0; mt < 2; mt++)
#pragma unroll
        for (int nt = 0; nt < 8; nt++)
#pragma unroll
            for (int i = 0; i < 4; i++) acc[mt][nt][i] = 0.f;

    const uint4 z4 = make_uint4(0, 0, 0, 0);

#pragma unroll 1
    for (int tap = 0; tap < 9; tap++) {
        int ky = tap / 3, kx = tap % 3;
        __syncthreads();

#pragma unroll
        for (int j = 0; j < 8; j++) {
            int s = j * 128 + tid;
            int v = s & 3;
            int m = (s >> 2) & 127;
            int p = s >> 9;
            int row = m >> 6, ox = m & 63;
            int oy = oy0 + row;
            int iy = 2 * oy + ky, ix = 2 * ox + kx;
            uint4 val = z4;
            if (iy < 128 && ix < 128) {
                const __nv_bfloat16* src = (p ? g_c1l : g_c1h)
                    + ((size_t)(b * 128 + iy) * 128 + ix) * 32 + v * 8;
                val = *(const uint4*)src;
            }
            *(uint4*)(&sA[p][m * 40 + v * 8]) = val;
        }
#pragma unroll
        for (int j = 0; j < 4; j++) {
            int s = j * 128 + tid;
            int v = s & 3;
            int n = (s >> 2) & 63;
            int p = s >> 8;
            const __nv_bfloat16* src = (p ? g_k2l : g_k2h)
                + ((size_t)tap * 64 + n) * 32 + v * 8;
            *(uint4*)(&sB[p][n * 40 + v * 8]) = *(const uint4*)src;
        }
        __syncthreads();

#pragma unroll
        for (int ksub = 0; ksub < 2; ksub++) {
            uint32_t aH[2][4], aL[2][4];
            {
                int rowf = (lane & 15);
                int colf = ksub * 16 + ((lane >> 4) << 3);
#pragma unroll
                for (int mt = 0; mt < 2; mt++) {
                    uint32_t off = (uint32_t)((wid * 32 + mt * 16 + rowf) * 40 + colf) * 2;
                    ldmx4(aH[mt], smem_u32(sA[0]) + off);
                    ldmx4(aL[mt], smem_u32(sA[1]) + off);
                }
            }
            uint32_t bH[8][2], bL[8][2];
            {
                int nf = ((lane >> 4) & 1) * 8 + (lane & 7);
                int kf = ksub * 16 + ((lane >> 3) & 1) * 8;
#pragma unroll
                for (int ntp = 0; ntp < 4; ntp++) {
                    uint32_t off = (uint32_t)((ntp * 16 + nf) * 40 + kf) * 2;
                    uint32_t r[4];
                    ldmx4(r, smem_u32(sB[0]) + off);
                    bH[2 * ntp][0] = r[0]; bH[2 * ntp][1] = r[1];
                    bH[2 * ntp + 1][0] = r[2]; bH[2 * ntp + 1][1] = r[3];
                    ldmx4(r, smem_u32(sB[1]) + off);
                    bL[2 * ntp][0] = r[0]; bL[2 * ntp][1] = r[1];
                    bL[2 * ntp + 1][0] = r[2]; bL[2 * ntp + 1][1] = r[3];
                }
            }
#pragma unroll
            for (int mt = 0; mt < 2; mt++)
#pragma unroll
                for (int nt = 0; nt < 8; nt++) {
                    mma16816(acc[mt][nt], aH[mt], bH[nt]);
                    mma16816(acc[mt][nt], aH[mt], bL[nt]);
                    mma16816(acc[mt][nt], aL[mt], bH[nt]);
                }
        }
    }

#pragma unroll
    for (int mt = 0; mt < 2; mt++) {
        int r0 = wid * 32 + mt * 16 + (lane >> 2);
        int r1 = r0 + 8;
        int px0 = b * 4096 + (oy0 + (r0 >> 6)) * 64 + (r0 & 63);
        int px1 = b * 4096 + (oy0 + (r1 >> 6)) * 64 + (r1 & 63);
#pragma unroll
        for (int nt = 0; nt < 8; nt++) {
            int c = nt * 8 + (lane & 3) * 2;
            float bc0 = b2[c], bc1 = b2[c + 1];
            float2 v0, v1;
            v0.x = fmaxf(acc[mt][nt][0] + bc0, 0.f);
            v0.y = fmaxf(acc[mt][nt][1] + bc1, 0.f);
            v1.x = fmaxf(acc[mt][nt][2] + bc0, 0.f);
            v1.y = fmaxf(acc[mt][nt][3] + bc1, 0.f);
            *(float2*)(g_c2 + (size_t)px0 * 64 + c) = v0;
            *(float2*)(g_c2 + (size_t)px1 * 64 + c) = v1;
        }
    }
}

// ============================================================================
// FC1 via warp-level bf16 MMA, 2-term split. y[32,128] = x[32,262144] @ w1.
// 512 blocks x 128 threads; chunk = 512 K-rows, 4 sub-chunks of 128.
// A = x staged [b][k] bf16 hi/lo, pitch 136 (proven conflict-free pattern).
// B = w1 staged [k][n] bf16 hi/lo, fragments via ldmatrix.x4.trans.
// Warp w owns n-columns [32w, 32w+32) = 4 n-tiles. Partials -> g_part (same
// reduce path as before).
// ============================================================================
__global__ void __launch_bounds__(128) fc1_mma(const float* __restrict__ w1) {
    extern __shared__ __align__(16) char smem[];
    __nv_bfloat16* sXh = (__nv_bfloat16*)(smem);            //  8704 B (32x136)
    __nv_bfloat16* sXl = (__nv_bfloat16*)(smem + 8704);     //  8704 B
    __nv_bfloat16* sWh = (__nv_bfloat16*)(smem + 17408);    // 34816 B (128x136)
    __nv_bfloat16* sWl = (__nv_bfloat16*)(smem + 52224);    // 34816 B -> 87040 total

    int tid = threadIdx.x;
    int wid = tid >> 5, lane = tid & 31;
    int i0 = blockIdx.x * 512;

    float acc[2][4][4];
#pragma unroll
    for (int mt = 0; mt < 2; mt++)
#pragma unroll
        for (int nt = 0; nt < 4; nt++)
#pragma unroll
            for (int i = 0; i < 4; i++) acc[mt][nt][i] = 0.f;

    uint32_t xh_u = smem_u32(sXh), xl_u = smem_u32(sXl);
    uint32_t wh_u = smem_u32(sWh), wl_u = smem_u32(sWl);

#pragma unroll 1
    for (int s = 0; s < 4; s++) {
        int k0 = i0 + s * 128;
        __syncthreads();

        // ---- stage X: 32 b x 128 k fp32 -> bf16 hi/lo; 8 float4/thread ----
#pragma unroll
        for (int j = 0; j < 8; j++) {
            int slot = j * 128 + tid;
            int b = slot >> 5, k4 = slot & 31;
            float4 v = *(const float4*)(g_c2 + (size_t)b * 262144 + k0 + k4 * 4);
            float f[4] = {v.x, v.y, v.z, v.w};
            __align__(8) __nv_bfloat16 h[4], l[4];
#pragma unroll
            for (int e = 0; e < 4; e++) {
                __nv_bfloat16 hh = __float2bfloat16_rn(f[e]);
                h[e] = hh;
                l[e] = __float2bfloat16_rn(f[e] - __bfloat162float(hh));
            }
            *(uint2*)(sXh + b * 136 + k4 * 4) = *(uint2*)h;
            *(uint2*)(sXl + b * 136 + k4 * 4) = *(uint2*)l;
        }

        // ---- stage W: 128 k x 128 n fp32 -> bf16 hi/lo; 32 float4/thread ----
#pragma unroll 4
        for (int j = 0; j < 32; j++) {
            int slot = j * 128 + tid;
            int k = slot >> 5, n4 = slot & 31;
            float4 v = *(const float4*)(w1 + (size_t)(k0 + k) * 128 + n4 * 4);
            float f[4] = {v.x, v.y, v.z, v.w};
            __align__(8) __nv_bfloat16 h[4], l[4];
#pragma unroll
            for (int e = 0; e < 4; e++) {
                __nv_bfloat16 hh = __float2bfloat16_rn(f[e]);
                h[e] = hh;
                l[e] = __float2bfloat16_rn(f[e] - __bfloat162float(hh));
            }
            *(uint2*)(sWh + k * 136 + n4 * 4) = *(uint2*)h;
            *(uint2*)(sWl + k * 136 + n4 * 4) = *(uint2*)l;
        }
        __syncthreads();

        // ---- compute: 8 ksubs x (2 m-tiles x 4 n-tiles x 3 splits) ----
        int rowf = lane & 15;
        int colf = (lane >> 4) << 3;
#pragma unroll
        for (int ksub = 0; ksub < 8; ksub++) {
            int k = ksub * 16;
            uint32_t aH[2][4], aL[2][4];
#pragma unroll
            for (int mt = 0; mt < 2; mt++) {
                uint32_t off = (uint32_t)((mt * 16 + rowf) * 136 + k + colf) * 2;
                ldmx4(aH[mt], xh_u + off);
                ldmx4(aL[mt], xl_u + off);
            }
            uint32_t bH[4][2], bL[4][2];
#pragma unroll
            for (int p = 0; p < 2; p++) {
                uint32_t off = (uint32_t)((k + rowf) * 136 + wid * 32 + p * 16 + colf) * 2;
                uint32_t r[4];
                ldmx4t(r, wh_u + off);
                bH[2 * p][0] = r[0]; bH[2 * p][1] = r[1];
                bH[2 * p + 1][0] = r[2]; bH[2 * p + 1][1] = r[3];
                ldmx4t(r, wl_u + off);
                bL[2 * p][0] = r[0]; bL[2 * p][1] = r[1];
                bL[2 * p + 1][0] = r[2]; bL[2 * p + 1][1] = r[3];
            }
#pragma unroll
            for (int mt = 0; mt < 2; mt++)
#pragma unroll
                for (int nt = 0; nt < 4; nt++) {
                    mma16816(acc[mt][nt], aH[mt], bH[nt]);
                    mma16816(acc[mt][nt], aH[mt], bL[nt]);
                    mma16816(acc[mt][nt], aL[mt], bH[nt]);
                }
        }
    }

    // ---- epilogue: write partial y[32][128] for this chunk ----
    float* P = g_part + (size_t)blockIdx.x * 4096;
#pragma unroll
    for (int mt = 0; mt < 2; mt++) {
        int m0 = mt * 16 + (lane >> 2);
        int m1 = m0 + 8;
#pragma unroll
        for (int nt = 0; nt < 4; nt++) {
            int c = wid * 32 + nt * 8 + (lane & 3) * 2;
            float2 v0 = make_float2(acc[mt][nt][0], acc[mt][nt][1]);
            float2 v1 = make_float2(acc[mt][nt][2], acc[mt][nt][3]);
            *(float2*)(P + m0 * 128 + c) = v0;
            *(float2*)(P + m1 * 128 + c) = v1;
        }
    }
}

// ---------------- reduce stage 1: 512 chunks -> 16 partials ----------------
__global__ void __launch_bounds__(128) reduce1_k() {
    int bx = blockIdx.x;
    int t  = (bx & 31) * 128 + threadIdx.x;
    int c0 = (bx >> 5) * 32;
    float s0 = 0.f, s1 = 0.f, s2 = 0.f, s3 = 0.f;
    for (int c = 0; c < 32; c += 4) {
        s0 += g_part[(size_t)(c0 + c + 0) * 4096 + t];
        s1 += g_part[(size_t)(c0 + c + 1) * 4096 + t];
        s2 += g_part[(size_t)(c0 + c + 2) * 4096 + t];
        s3 += g_part[(size_t)(c0 + c + 3) * 4096 + t];
    }
    g_part2[(size_t)(bx >> 5) * 4096 + t] = (s0 + s1) + (s2 + s3);
}

// ---------------- reduce stage 2: 16 -> 1 ----------------
__global__ void __launch_bounds__(128) reduce2_k() {
    int t = blockIdx.x * 128 + threadIdx.x;
    float s = 0.f;
#pragma unroll
    for (int g = 0; g < 16; g++) s += g_part2[(size_t)g * 4096 + t];
    g_fc1[t] = s;
}

// ---------------- FC2 ----------------
__global__ void fc2_k(const float* __restrict__ d1,
                      const float* __restrict__ w2,
                      const float* __restrict__ d2) {
    int t = threadIdx.x;
    if (t < 192) {
        int b = t / 6, k = t % 6;
        float s = d2[k];
        for (int j = 0; j < 128; j++) {
            float xv = fmaxf(g_fc1[b * 128 + j] + d1[j], 0.f);
            s += xv * w2[j * 6 + k];
        }
        g_theta[t] = s;
    }
}

// ---------------- bilinear grid sample, zero padding ----------------
__global__ void __launch_bounds__(256) sample_k(const float* __restrict__ img,
                                                float* __restrict__ out) {
    int idx = blockIdx.x * 256 + threadIdx.x;
    int x = idx & 255;
    int y = (idx >> 8) & 255;
    int b = idx >> 16;

    const float* t = g_theta + b * 6;
    float X = (2.f * x + 1.f) * (1.f / 256.f) - 1.f;
    float Y = (2.f * y + 1.f) * (1.f / 256.f) - 1.f;
    float gx = t[0] * X + t[1] * Y + t[2];
    float gy = t[3] * X + t[4] * Y + t[5];
    float px = (gx + 1.f) * 128.f - 0.5f;
    float py = (gy + 1.f) * 128.f - 0.5f;

    float x0f = floorf(px), y0f = floorf(py);
    float wx1 = px - x0f, wx0 = 1.f - wx1;
    float wy1 = py - y0f, wy0 = 1.f - wy1;
    int x0 = (int)x0f, y0 = (int)y0f;

    const float* base = img + (size_t)b * 256 * 256 * 3;
    float r = 0.f, g = 0.f, bl = 0.f;

#pragma unroll
    for (int c = 0; c < 4; c++) {
        int yi = y0 + (c >> 1);
        int xi = x0 + (c & 1);
        float wgt = ((c >> 1) ? wy1 : wy0) * ((c & 1) ? wx1 : wx0);
        if (xi >= 0 && xi < 256 && yi >= 0 && yi < 256) {
            const float* p = base + ((size_t)yi * 256 + xi) * 3;
            r  += p[0] * wgt;
            g  += p[1] * wgt;
            bl += p[2] * wgt;
        }
    }

    float* o = out + (size_t)idx * 3;
    o[0] = r; o[1] = g; o[2] = bl;
}

// ---------------- launch ----------------
extern "C" void kernel_launch(void* const* d_in, const int* in_sizes, int n_in,
                              void* d_out, int out_size) {
    const float* inputs = (const float*)d_in[0];
    const float* k1 = (const float*)d_in[1];
    const float* b1 = (const float*)d_in[2];
    const float* k2 = (const float*)d_in[3];
    const float* b2 = (const float*)d_in[4];
    const float* w1 = (const float*)d_in[5];
    const float* d1 = (const float*)d_in[6];
    const float* w2 = (const float*)d_in[7];
    const float* d2 = (const float*)d_in[8];
    float* out = (float*)d_out;

    cudaFuncSetAttribute(fc1_mma, cudaFuncAttributeMaxDynamicSharedMemorySize, 87040);

    conv1_k<<<2048, 128>>>(inputs, k1, b1);     // slot 0
    wprep_k<<<80, 256>>>(k2);                   // slot 1
    conv2_mma<<<1024, 128>>>(b2);               // slot 2
    fc1_mma<<<512, 128, 87040>>>(w1);           // slot 3  <- profiled
    reduce1_k<<<512, 128>>>();
    reduce2_k<<<32, 128>>>();
    fc2_k<<<1, 192>>>(d1, w2, d2);
    sample_k<<<8192, 256>>>(inputs, out);
}